// round 1
// baseline (speedup 1.0000x reference)
#include <cuda_runtime.h>
#include <cstdint>
#include <cstdio>

// Problem dimensions (fixed by the dataset)
#define NN 50000
#define EE 400000
#define MM 800000
#define HH 128
#define HM 256
#define BN_EPS 1e-5f

// ---------------- device scratch (no allocation allowed) ----------------
__device__ float g_lift[(size_t)EE * HH];   // lift_aggr [E,128]
__device__ float g_y1  [(size_t)EE * HH];   // concat@Wa raw, then BN-ReLU in place
__device__ float g_lvl [(size_t)NN * HH];   // lvl_aggr [N,128]
__device__ float g_yb1 [(size_t)NN * HM];   // hn@Wb1 raw
__device__ float g_yl1 [(size_t)EE * HM];   // he@Wl1 raw

// BN stats: 5 norms, up to 256 cols each
__device__ float g_sum  [5 * 256];
__device__ float g_sumsq[5 * 256];
__device__ float g_scale[5 * 256];
__device__ float g_shift[5 * 256];

// ---------------- scatter: out[sidx[m]] += vals[gidx[m]] (rows of 128) ----------------
__global__ void k_scatter(const float* __restrict__ vals,
                          const int*   __restrict__ gidx,
                          const int*   __restrict__ sidx,
                          float*       __restrict__ out)
{
    int t = blockIdx.x * blockDim.x + threadIdx.x;
    int m = t >> 5;
    if (m >= MM) return;
    int lane = t & 31;
    int g = __ldg(gidx + m);
    int s = __ldg(sidx + m);
    float4 v = *(const float4*)(vals + (size_t)g * HH + lane * 4);
    float* o = out + (size_t)s * HH + lane * 4;
    atomicAdd(o + 0, v.x);
    atomicAdd(o + 1, v.y);
    atomicAdd(o + 2, v.z);
    atomicAdd(o + 3, v.w);
}

// ---------------- GEMM: C[Rows,Ncols] = A[Rows,K] @ B[K,Ncols] ----------------
// MODE 1: A = concat(A0[.,128], A1[.,128])           (K = 256)
// MODE 2: A = (1+*epsp)*A0 + A1                       (K = 128)
// MODE 3: A = relu(A0 * scl[k] + shf[k])              (BN-ReLU fused on load)
#define BM 64
#define BN_ 128
#define BK 32
#define TM 8
#define TN 4

template <int MODE>
__global__ __launch_bounds__(256)
void k_gemm(const float* __restrict__ A0, const float* __restrict__ A1,
            const float* __restrict__ scl, const float* __restrict__ shf,
            const float* __restrict__ epsp,
            const float* __restrict__ B, float* __restrict__ C,
            int Rows, int K, int Ncols)
{
    __shared__ float As[BK][BM];    // transposed: As[k][row]
    __shared__ float Bs[BK][BN_];

    int tid = threadIdx.x;
    int ty = tid >> 5;   // 0..7  -> row group of 8
    int tx = tid & 31;   // 0..31 -> col group of 4
    int r0 = blockIdx.x * BM;
    int c0 = blockIdx.y * BN_;

    float acc[TM][TN];
#pragma unroll
    for (int i = 0; i < TM; i++)
#pragma unroll
        for (int j = 0; j < TN; j++) acc[i][j] = 0.f;

    float et = 1.0f;
    if (MODE == 2) et = 1.0f + *epsp;

    for (int kt = 0; kt < K; kt += BK) {
        // ---- load A tile: 64 rows x 32 k (2048 floats, 2 float4/thread)
#pragma unroll
        for (int l = 0; l < 2; l++) {
            int idx  = tid * 2 + l;       // 0..511
            int row  = idx >> 3;          // 0..63
            int quad = idx & 7;           // 0..7
            int gr = r0 + row;
            int k  = kt + quad * 4;
            float4 v = make_float4(0.f, 0.f, 0.f, 0.f);
            if (gr < Rows) {
                if (MODE == 1) {
                    if (k < 128) v = *(const float4*)(A0 + (size_t)gr * 128 + k);
                    else         v = *(const float4*)(A1 + (size_t)gr * 128 + (k - 128));
                } else if (MODE == 2) {
                    float4 x = *(const float4*)(A0 + (size_t)gr * 128 + k);
                    float4 y = *(const float4*)(A1 + (size_t)gr * 128 + k);
                    v.x = fmaf(et, x.x, y.x);
                    v.y = fmaf(et, x.y, y.y);
                    v.z = fmaf(et, x.z, y.z);
                    v.w = fmaf(et, x.w, y.w);
                } else { // MODE 3
                    float4 r  = *(const float4*)(A0 + (size_t)gr * K + k);
                    float4 s4 = *(const float4*)(scl + k);
                    float4 h4 = *(const float4*)(shf + k);
                    v.x = fmaxf(fmaf(r.x, s4.x, h4.x), 0.f);
                    v.y = fmaxf(fmaf(r.y, s4.y, h4.y), 0.f);
                    v.z = fmaxf(fmaf(r.z, s4.z, h4.z), 0.f);
                    v.w = fmaxf(fmaf(r.w, s4.w, h4.w), 0.f);
                }
            }
            As[quad * 4 + 0][row] = v.x;
            As[quad * 4 + 1][row] = v.y;
            As[quad * 4 + 2][row] = v.z;
            As[quad * 4 + 3][row] = v.w;
        }
        // ---- load B tile: 32 x 128 (4096 floats, 4 float4/thread)
#pragma unroll
        for (int l = 0; l < 4; l++) {
            int idx  = l * 256 + tid;     // 0..1023
            int row  = idx >> 5;          // 0..31
            int colq = idx & 31;          // 0..31
            float4 v = *(const float4*)(B + (size_t)(kt + row) * Ncols + c0 + colq * 4);
            Bs[row][colq * 4 + 0] = v.x;
            Bs[row][colq * 4 + 1] = v.y;
            Bs[row][colq * 4 + 2] = v.z;
            Bs[row][colq * 4 + 3] = v.w;
        }
        __syncthreads();

#pragma unroll
        for (int kk = 0; kk < BK; kk++) {
            float a[TM], b[TN];
#pragma unroll
            for (int i = 0; i < TM; i++) a[i] = As[kk][ty * TM + i];
#pragma unroll
            for (int j = 0; j < TN; j++) b[j] = Bs[kk][tx * TN + j];
#pragma unroll
            for (int i = 0; i < TM; i++)
#pragma unroll
                for (int j = 0; j < TN; j++) acc[i][j] = fmaf(a[i], b[j], acc[i][j]);
        }
        __syncthreads();
    }

#pragma unroll
    for (int i = 0; i < TM; i++) {
        int gr = r0 + ty * TM + i;
        if (gr < Rows) {
            float4 v = make_float4(acc[i][0], acc[i][1], acc[i][2], acc[i][3]);
            *(float4*)(C + (size_t)gr * Ncols + c0 + tx * TN) = v;
        }
    }
}

// ---------------- per-column sums for BN stats ----------------
__global__ void k_stats(const float* __restrict__ X, int rows, int C,
                        float* __restrict__ sum, float* __restrict__ sumsq)
{
    int tid = threadIdx.x;
    int perRow = 256 / C;            // 2 for C=128, 1 for C=256
    int col = tid % C;
    int sub = tid / C;
    float s = 0.f, ss = 0.f;
    for (long long r = (long long)blockIdx.x * perRow + sub; r < rows;
         r += (long long)gridDim.x * perRow) {
        float v = X[r * C + col];
        s += v; ss += v * v;
    }
    if (C == 128) {
        __shared__ float sh[512];
        sh[tid] = s; sh[256 + tid] = ss;
        __syncthreads();
        if (tid < 128) {
            s  += sh[tid + 128];
            ss += sh[256 + tid + 128];
            atomicAdd(sum + col, s);
            atomicAdd(sumsq + col, ss);
        }
    } else {
        atomicAdd(sum + col, s);
        atomicAdd(sumsq + col, ss);
    }
}

// ---------------- BN scale/shift from sums ----------------
__global__ void k_finalize(int C, float invR,
                           const float* __restrict__ g, const float* __restrict__ b,
                           const float* __restrict__ sum, const float* __restrict__ sumsq,
                           float* __restrict__ scale, float* __restrict__ shift)
{
    int c = threadIdx.x;
    if (c < C) {
        float m   = sum[c] * invR;
        float var = sumsq[c] * invR - m * m;
        float s   = g[c] * rsqrtf(var + BN_EPS);
        scale[c] = s;
        shift[c] = b[c] - m * s;
    }
}

// ---------------- in-place BN affine + ReLU ----------------
__global__ void k_apply(float* __restrict__ X, long long n4, int cmask4,
                        const float* __restrict__ scale, const float* __restrict__ shift)
{
    for (long long idx = blockIdx.x * (long long)blockDim.x + threadIdx.x; idx < n4;
         idx += (long long)gridDim.x * blockDim.x) {
        int c4 = (int)(idx & cmask4);
        float4 v  = ((float4*)X)[idx];
        float4 sc = *(const float4*)(scale + c4 * 4);
        float4 sh = *(const float4*)(shift + c4 * 4);
        v.x = fmaxf(fmaf(v.x, sc.x, sh.x), 0.f);
        v.y = fmaxf(fmaf(v.y, sc.y, sh.y), 0.f);
        v.z = fmaxf(fmaf(v.z, sc.z, sh.z), 0.f);
        v.w = fmaxf(fmaf(v.w, sc.w, sh.w), 0.f);
        ((float4*)X)[idx] = v;
    }
}

// ---------------- launch ----------------
extern "C" void kernel_launch(void* const* d_in, const int* in_sizes, int n_in,
                              void* d_out, int out_size)
{
    const float* node_rep = (const float*)d_in[0];
    const float* edge_rep = (const float*)d_in[1];
    const int*   n2e      = (const int*)  d_in[2];
    const int*   src = n2e;           // node index per incidence
    const int*   dst = n2e + MM;      // edge index per incidence
    const float* Wa  = (const float*)d_in[3];
    const float* ga  = (const float*)d_in[4];
    const float* ba  = (const float*)d_in[5];
    const float* Wb1 = (const float*)d_in[6];
    const float* gb1 = (const float*)d_in[7];
    const float* bb1 = (const float*)d_in[8];
    const float* Wb2 = (const float*)d_in[9];
    const float* gb2 = (const float*)d_in[10];
    const float* bb2 = (const float*)d_in[11];
    const float* Wl1 = (const float*)d_in[12];
    const float* gl1 = (const float*)d_in[13];
    const float* bl1 = (const float*)d_in[14];
    const float* Wl2 = (const float*)d_in[15];
    const float* gl2 = (const float*)d_in[16];
    const float* bl2 = (const float*)d_in[17];
    const float* eps1 = (const float*)d_in[18];
    const float* eps2 = (const float*)d_in[19];

    float* out_node = (float*)d_out;                     // [N,128]
    float* out_edge = out_node + (size_t)NN * HH;        // [E,128]

    float *p_lift, *p_y1, *p_lvl, *p_yb1, *p_yl1;
    float *p_sum, *p_sumsq, *p_scale, *p_shift;
    cudaGetSymbolAddress((void**)&p_lift,  g_lift);
    cudaGetSymbolAddress((void**)&p_y1,    g_y1);
    cudaGetSymbolAddress((void**)&p_lvl,   g_lvl);
    cudaGetSymbolAddress((void**)&p_yb1,   g_yb1);
    cudaGetSymbolAddress((void**)&p_yl1,   g_yl1);
    cudaGetSymbolAddress((void**)&p_sum,   g_sum);
    cudaGetSymbolAddress((void**)&p_sumsq, g_sumsq);
    cudaGetSymbolAddress((void**)&p_scale, g_scale);
    cudaGetSymbolAddress((void**)&p_shift, g_shift);

    cudaMemsetAsync(p_lift, 0, (size_t)EE * HH * sizeof(float));
    cudaMemsetAsync(p_lvl,  0, (size_t)NN * HH * sizeof(float));
    cudaMemsetAsync(p_sum,  0, 5 * 256 * sizeof(float));
    cudaMemsetAsync(p_sumsq,0, 5 * 256 * sizeof(float));

    const int scatter_blocks = (MM * 32 + 255) / 256;

    // 1) lift_aggr[dst] += node_rep[src]
    k_scatter<<<scatter_blocks, 256>>>(node_rep, src, dst, p_lift);

    // 2) y1 = concat(lift, edge) @ Wa   [E,128]
    k_gemm<1><<<dim3((EE + BM - 1) / BM, 1), 256>>>(
        p_lift, edge_rep, nullptr, nullptr, nullptr, Wa, p_y1, EE, 256, 128);
    k_stats<<<512, 256>>>(p_y1, EE, 128, p_sum + 0, p_sumsq + 0);
    k_finalize<<<1, 256>>>(128, 1.f / EE, ga, ba, p_sum + 0, p_sumsq + 0,
                           p_scale + 0, p_shift + 0);
    k_apply<<<2048, 256>>>(p_y1, (long long)EE * HH / 4, 31, p_scale + 0, p_shift + 0);

    // 3) lvl_aggr[src] += y1[dst]
    k_scatter<<<scatter_blocks, 256>>>(p_y1, dst, src, p_lvl);

    // 4) node branch: yb1 = ((1+eps1)*node_rep + lvl) @ Wb1  [N,256]
    k_gemm<2><<<dim3((NN + BM - 1) / BM, 2), 256>>>(
        node_rep, p_lvl, nullptr, nullptr, eps1, Wb1, p_yb1, NN, 128, 256);
    k_stats<<<512, 256>>>(p_yb1, NN, 256, p_sum + 256, p_sumsq + 256);
    k_finalize<<<1, 256>>>(256, 1.f / NN, gb1, bb1, p_sum + 256, p_sumsq + 256,
                           p_scale + 256, p_shift + 256);
    // node_out_raw = BNReLU(yb1) @ Wb2  [N,128]  (BN-ReLU fused on A-load)
    k_gemm<3><<<dim3((NN + BM - 1) / BM, 1), 256>>>(
        p_yb1, nullptr, p_scale + 256, p_shift + 256, nullptr, Wb2, out_node, NN, 256, 128);
    k_stats<<<512, 256>>>(out_node, NN, 128, p_sum + 512, p_sumsq + 512);
    k_finalize<<<1, 256>>>(128, 1.f / NN, gb2, bb2, p_sum + 512, p_sumsq + 512,
                           p_scale + 512, p_shift + 512);
    k_apply<<<2048, 256>>>(out_node, (long long)NN * HH / 4, 31, p_scale + 512, p_shift + 512);

    // 5) edge branch: yl1 = ((1+eps2)*edge_rep + lift) @ Wl1  [E,256]
    k_gemm<2><<<dim3((EE + BM - 1) / BM, 2), 256>>>(
        edge_rep, p_lift, nullptr, nullptr, eps2, Wl1, p_yl1, EE, 128, 256);
    k_stats<<<512, 256>>>(p_yl1, EE, 256, p_sum + 768, p_sumsq + 768);
    k_finalize<<<1, 256>>>(256, 1.f / EE, gl1, bl1, p_sum + 768, p_sumsq + 768,
                           p_scale + 768, p_shift + 768);
    // edge_out_raw = BNReLU(yl1) @ Wl2  [E,128]
    k_gemm<3><<<dim3((EE + BM - 1) / BM, 1), 256>>>(
        p_yl1, nullptr, p_scale + 768, p_shift + 768, nullptr, Wl2, out_edge, EE, 256, 128);
    k_stats<<<512, 256>>>(out_edge, EE, 128, p_sum + 1024, p_sumsq + 1024);
    k_finalize<<<1, 256>>>(128, 1.f / EE, gl2, bl2, p_sum + 1024, p_sumsq + 1024,
                           p_scale + 1024, p_shift + 1024);
    k_apply<<<2048, 256>>>(out_edge, (long long)EE * HH / 4, 31, p_scale + 1024, p_shift + 1024);
}

// round 3
// speedup vs baseline: 1.5372x; 1.5372x over previous
#include <cuda_runtime.h>
#include <cstdint>

#define NN 50000
#define EE 400000
#define MM 800000
#define HH 128
#define HM 256
#define BN_EPS 1e-5f

// ---------------- device scratch ----------------
__device__ float g_lift[(size_t)EE * HH];
__device__ float g_y1  [(size_t)EE * HH];
__device__ float g_lvl [(size_t)NN * HH];
__device__ float g_yb1 [(size_t)NN * HM];
__device__ float g_yl1 [(size_t)EE * HM];
__device__ float g_wt  [5 * 65536];          // transposed weights [N,K]
__device__ float g_sum  [5 * 256];
__device__ float g_sumsq[5 * 256];
__device__ float g_scale[5 * 256];
__device__ float g_shift[5 * 256];

// ---------------- helpers ----------------
__device__ __forceinline__ float f2tf(float x) {
    uint32_t r;
    asm("cvt.rna.tf32.f32 %0, %1;" : "=r"(r) : "f"(x));
    return __uint_as_float(r);
}
__device__ __forceinline__ void mma_tf32(float* c, const uint32_t* a, const uint32_t* b) {
    asm volatile("mma.sync.aligned.m16n8k8.row.col.f32.tf32.tf32.f32 "
                 "{%0,%1,%2,%3}, {%4,%5,%6,%7}, {%8,%9}, {%0,%1,%2,%3};"
                 : "+f"(c[0]), "+f"(c[1]), "+f"(c[2]), "+f"(c[3])
                 : "r"(a[0]), "r"(a[1]), "r"(a[2]), "r"(a[3]),
                   "r"(b[0]), "r"(b[1]));
}

// ---------------- scatter: out[sidx[m]] += vals[gidx[m]] (rows of 128) ----------------
__global__ void k_scatter(const float* __restrict__ vals,
                          const int*   __restrict__ gidx,
                          const int*   __restrict__ sidx,
                          float*       __restrict__ out)
{
    int t = blockIdx.x * blockDim.x + threadIdx.x;
    int m = t >> 5;
    if (m >= MM) return;
    int lane = t & 31;
    int g = __ldg(gidx + m);
    int s = __ldg(sidx + m);
    float4 v = *(const float4*)(vals + (size_t)g * HH + lane * 4);
    float* o = out + (size_t)s * HH + lane * 4;
    atomicAdd(o + 0, v.x);
    atomicAdd(o + 1, v.y);
    atomicAdd(o + 2, v.z);
    atomicAdd(o + 3, v.w);
}

// ---------------- weight transpose: Wt[n*K+k] = W[k*NC+n] ----------------
__global__ void k_transpose(const float* __restrict__ W, float* __restrict__ Wt, int K, int NC)
{
    int i = blockIdx.x * blockDim.x + threadIdx.x;
    if (i < K * NC) {
        int k = i / NC, n = i % NC;
        Wt[(size_t)n * K + k] = W[i];
    }
}

// ---------------- tf32 mma.sync GEMM: C[Rows,Ncols] = A[Rows,K] @ Bt^T ----------------
// CTA tile 128x128 (blockIdx.y = 128-col slice). Fused BN column stats in epilogue.
// MODE 1: A = concat(A0[.,128], A1[.,128])   (K=256)
// MODE 2: A = (1+*epsp)*A0 + A1              (K=128)
// MODE 3: A = relu(A0*scl[k] + shf[k])       (K=256, BN-ReLU fused on load)
template <int MODE, int K>
__global__ __launch_bounds__(256)
void k_gemm_mma(const float* __restrict__ A0, const float* __restrict__ A1,
                const float* __restrict__ scl, const float* __restrict__ shf,
                const float* __restrict__ epsp,
                const float* __restrict__ Bt,      // [Ncols, K]
                float* __restrict__ C, int Rows, int Ncols,
                float* __restrict__ osum, float* __restrict__ osumsq)
{
    extern __shared__ float smem[];
    float* sA = smem;          // [2][4096] fragment-order A tiles
    float* sB = smem + 8192;   // [2][4096] fragment-order B tiles

    constexpr int NCH = K / 32;

    int tid = threadIdx.x;
    int lane = tid & 31, wid = tid >> 5;
    int wm = wid >> 1, wn = wid & 1;          // 4x2 warp grid
    int r0 = blockIdx.x * 128;
    int c0 = blockIdx.y * 128;
    const float* Bs = Bt + (size_t)c0 * K;

    float et = 1.0f;
    if (MODE == 2) et = 1.0f + *epsp;

    float4 areg[4], breg[4];

    // ---- global load of one 128x32 A chunk (transform fused) ----
    auto loadA = [&](int ch) {
        int kt = ch * 32;
#pragma unroll
        for (int i = 0; i < 4; i++) {
            int idx = i * 256 + tid;
            int row = idx >> 3, q = idx & 7;
            int gr = r0 + row, k = kt + q * 4;
            float4 v = make_float4(0.f, 0.f, 0.f, 0.f);
            if (gr < Rows) {
                if (MODE == 1) {
                    const float* s = (k < 128) ? A0 + (size_t)gr * 128 + k
                                               : A1 + (size_t)gr * 128 + (k - 128);
                    v = *(const float4*)s;
                } else if (MODE == 2) {
                    float4 x = *(const float4*)(A0 + (size_t)gr * 128 + k);
                    float4 y = *(const float4*)(A1 + (size_t)gr * 128 + k);
                    v.x = fmaf(et, x.x, y.x); v.y = fmaf(et, x.y, y.y);
                    v.z = fmaf(et, x.z, y.z); v.w = fmaf(et, x.w, y.w);
                } else {
                    float4 r4 = *(const float4*)(A0 + (size_t)gr * K + k);
                    float4 s4 = *(const float4*)(scl + k);
                    float4 h4 = *(const float4*)(shf + k);
                    v.x = fmaxf(fmaf(r4.x, s4.x, h4.x), 0.f);
                    v.y = fmaxf(fmaf(r4.y, s4.y, h4.y), 0.f);
                    v.z = fmaxf(fmaf(r4.z, s4.z, h4.z), 0.f);
                    v.w = fmaxf(fmaf(r4.w, s4.w, h4.w), 0.f);
                }
            }
            areg[i] = v;
        }
    };
    auto loadB = [&](int ch) {
        int kt = ch * 32;
#pragma unroll
        for (int i = 0; i < 4; i++) {
            int idx = i * 256 + tid;
            int n = idx >> 3, q = idx & 7;
            breg[i] = *(const float4*)(Bs + (size_t)n * K + kt + q * 4);
        }
    };
    // ---- store regs -> fragment-order smem (tf32 convert) ----
    // A frag layout: addr = ((mt*4+ks)*32 + (row&7)*4 + t)*4 + r, r = hi + 2*(kk>=4)
    auto stsA = [&](int buf) {
        float* d = sA + buf * 4096;
#pragma unroll
        for (int i = 0; i < 4; i++) {
            int idx = i * 256 + tid;
            int row = idx >> 3, q = idx & 7;
            int mt = row >> 4, ks = q >> 1;
            int r = ((row >> 3) & 1) + 2 * (q & 1);
            int base = ((mt * 4 + ks) * 32 + (row & 7) * 4) * 4 + r;
            d[base + 0 ] = f2tf(areg[i].x);
            d[base + 4 ] = f2tf(areg[i].y);
            d[base + 8 ] = f2tf(areg[i].z);
            d[base + 12] = f2tf(areg[i].w);
        }
    };
    // B frag layout: addr = ((nt*4+ks)*32 + (n&7)*4 + t)*2 + r, r = (kk>=4)
    auto stsB = [&](int buf) {
        float* d = sB + buf * 4096;
#pragma unroll
        for (int i = 0; i < 4; i++) {
            int idx = i * 256 + tid;
            int n = idx >> 3, q = idx & 7;
            int nt = n >> 3, ks = q >> 1, r = q & 1;
            int base = ((nt * 4 + ks) * 32 + (n & 7) * 4) * 2 + r;
            d[base + 0] = f2tf(breg[i].x);
            d[base + 2] = f2tf(breg[i].y);
            d[base + 4] = f2tf(breg[i].z);
            d[base + 6] = f2tf(breg[i].w);
        }
    };

    float acc[2][8][4];
#pragma unroll
    for (int mt = 0; mt < 2; mt++)
#pragma unroll
        for (int nt = 0; nt < 8; nt++)
#pragma unroll
            for (int r = 0; r < 4; r++) acc[mt][nt][r] = 0.f;

    loadA(0); loadB(0);
    stsA(0);  stsB(0);
    __syncthreads();

    for (int ch = 0; ch < NCH; ch++) {
        if (ch + 1 < NCH) { loadA(ch + 1); loadB(ch + 1); }
        int buf = ch & 1;
        const float* pa = sA + buf * 4096;
        const float* pb = sB + buf * 4096;
#pragma unroll
        for (int ks = 0; ks < 4; ks++) {
            uint4 av[2];
            uint2 bv[8];
#pragma unroll
            for (int mt = 0; mt < 2; mt++)
                av[mt] = *(const uint4*)(pa + (((wm * 2 + mt) * 4 + ks) * 32 + lane) * 4);
#pragma unroll
            for (int nt = 0; nt < 8; nt++)
                bv[nt] = *(const uint2*)(pb + (((wn * 8 + nt) * 4 + ks) * 32 + lane) * 2);
#pragma unroll
            for (int mt = 0; mt < 2; mt++)
#pragma unroll
                for (int nt = 0; nt < 8; nt++)
                    mma_tf32(acc[mt][nt], (const uint32_t*)&av[mt], (const uint32_t*)&bv[nt]);
        }
        if (ch + 1 < NCH) { stsA(buf ^ 1); stsB(buf ^ 1); }
        __syncthreads();
    }

    // ---- epilogue: store C + fused column stats ----
    int g = lane >> 2, t = lane & 3;
#pragma unroll
    for (int mt = 0; mt < 2; mt++) {
        int ra = r0 + wm * 32 + mt * 16 + g;
        int rb = ra + 8;
#pragma unroll
        for (int nt = 0; nt < 8; nt++) {
            int col = c0 + wn * 64 + nt * 8 + 2 * t;
            if (ra < Rows) {
                float2 v = make_float2(acc[mt][nt][0], acc[mt][nt][1]);
                *(float2*)(C + (size_t)ra * Ncols + col) = v;
            }
            if (rb < Rows) {
                float2 v = make_float2(acc[mt][nt][2], acc[mt][nt][3]);
                *(float2*)(C + (size_t)rb * Ncols + col) = v;
            }
        }
    }
    // column sums (padded rows contribute exact zeros)
#pragma unroll
    for (int nt = 0; nt < 8; nt++) {
#pragma unroll
        for (int p = 0; p < 2; p++) {
            float a0 = acc[0][nt][p],     a1 = acc[0][nt][p + 2];
            float a2 = acc[1][nt][p],     a3 = acc[1][nt][p + 2];
            float s  = a0 + a1 + a2 + a3;
            float ss = a0 * a0 + a1 * a1 + a2 * a2 + a3 * a3;
#pragma unroll
            for (int off = 4; off < 32; off <<= 1) {
                s  += __shfl_xor_sync(0xFFFFFFFFu, s,  off);
                ss += __shfl_xor_sync(0xFFFFFFFFu, ss, off);
            }
            if (g == 0) {
                int col = c0 + wn * 64 + nt * 8 + 2 * t + p;
                atomicAdd(osum + col, s);
                atomicAdd(osumsq + col, ss);
            }
        }
    }
}

// ---------------- BN scale/shift from sums ----------------
__global__ void k_finalize(int C, float invR,
                           const float* __restrict__ g, const float* __restrict__ b,
                           const float* __restrict__ sum, const float* __restrict__ sumsq,
                           float* __restrict__ scale, float* __restrict__ shift)
{
    int c = threadIdx.x;
    if (c < C) {
        float m   = sum[c] * invR;
        float var = sumsq[c] * invR - m * m;
        float s   = g[c] * rsqrtf(var + BN_EPS);
        scale[c] = s;
        shift[c] = b[c] - m * s;
    }
}

// ---------------- in-place BN affine + ReLU ----------------
__global__ void k_apply(float* __restrict__ X, long long n4, int cmask4,
                        const float* __restrict__ scale, const float* __restrict__ shift)
{
    for (long long idx = blockIdx.x * (long long)blockDim.x + threadIdx.x; idx < n4;
         idx += (long long)gridDim.x * blockDim.x) {
        int c4 = (int)(idx & cmask4);
        float4 v  = ((float4*)X)[idx];
        float4 sc = *(const float4*)(scale + c4 * 4);
        float4 sh = *(const float4*)(shift + c4 * 4);
        v.x = fmaxf(fmaf(v.x, sc.x, sh.x), 0.f);
        v.y = fmaxf(fmaf(v.y, sc.y, sh.y), 0.f);
        v.z = fmaxf(fmaf(v.z, sc.z, sh.z), 0.f);
        v.w = fmaxf(fmaf(v.w, sc.w, sh.w), 0.f);
        ((float4*)X)[idx] = v;
    }
}

// ---------------- launch ----------------
extern "C" void kernel_launch(void* const* d_in, const int* in_sizes, int n_in,
                              void* d_out, int out_size)
{
    const float* node_rep = (const float*)d_in[0];
    const float* edge_rep = (const float*)d_in[1];
    const int*   n2e      = (const int*)  d_in[2];
    const int*   src = n2e;
    const int*   dst = n2e + MM;
    const float* Wa  = (const float*)d_in[3];
    const float* ga  = (const float*)d_in[4];
    const float* ba  = (const float*)d_in[5];
    const float* Wb1 = (const float*)d_in[6];
    const float* gb1 = (const float*)d_in[7];
    const float* bb1 = (const float*)d_in[8];
    const float* Wb2 = (const float*)d_in[9];
    const float* gb2 = (const float*)d_in[10];
    const float* bb2 = (const float*)d_in[11];
    const float* Wl1 = (const float*)d_in[12];
    const float* gl1 = (const float*)d_in[13];
    const float* bl1 = (const float*)d_in[14];
    const float* Wl2 = (const float*)d_in[15];
    const float* gl2 = (const float*)d_in[16];
    const float* bl2 = (const float*)d_in[17];
    const float* eps1 = (const float*)d_in[18];
    const float* eps2 = (const float*)d_in[19];

    float* out_node = (float*)d_out;
    float* out_edge = out_node + (size_t)NN * HH;

    float *p_lift, *p_y1, *p_lvl, *p_yb1, *p_yl1, *p_wt;
    float *p_sum, *p_sumsq, *p_scale, *p_shift;
    cudaGetSymbolAddress((void**)&p_lift,  g_lift);
    cudaGetSymbolAddress((void**)&p_y1,    g_y1);
    cudaGetSymbolAddress((void**)&p_lvl,   g_lvl);
    cudaGetSymbolAddress((void**)&p_yb1,   g_yb1);
    cudaGetSymbolAddress((void**)&p_yl1,   g_yl1);
    cudaGetSymbolAddress((void**)&p_wt,    g_wt);
    cudaGetSymbolAddress((void**)&p_sum,   g_sum);
    cudaGetSymbolAddress((void**)&p_sumsq, g_sumsq);
    cudaGetSymbolAddress((void**)&p_scale, g_scale);
    cudaGetSymbolAddress((void**)&p_shift, g_shift);

    const int SMEM = 16384 * 4;   // 64 KB dynamic
    cudaFuncSetAttribute(k_gemm_mma<1, 256>, cudaFuncAttributeMaxDynamicSharedMemorySize, SMEM);
    cudaFuncSetAttribute(k_gemm_mma<2, 128>, cudaFuncAttributeMaxDynamicSharedMemorySize, SMEM);
    cudaFuncSetAttribute(k_gemm_mma<3, 256>, cudaFuncAttributeMaxDynamicSharedMemorySize, SMEM);

    cudaMemsetAsync(p_lift, 0, (size_t)EE * HH * sizeof(float));
    cudaMemsetAsync(p_lvl,  0, (size_t)NN * HH * sizeof(float));
    cudaMemsetAsync(p_sum,  0, 5 * 256 * sizeof(float));
    cudaMemsetAsync(p_sumsq,0, 5 * 256 * sizeof(float));

    // transpose weights -> [N, K]
    k_transpose<<<128, 256>>>(Wa,  p_wt + 0 * 65536, 256, 128);
    k_transpose<<<128, 256>>>(Wb1, p_wt + 1 * 65536, 128, 256);
    k_transpose<<<128, 256>>>(Wb2, p_wt + 2 * 65536, 256, 128);
    k_transpose<<<128, 256>>>(Wl1, p_wt + 3 * 65536, 128, 256);
    k_transpose<<<128, 256>>>(Wl2, p_wt + 4 * 65536, 256, 128);

    const int scatter_blocks = (MM * 32 + 255) / 256;
    const int gridE = (EE + 127) / 128;   // 3125
    const int gridN = (NN + 127) / 128;   // 391

    // 1) lift_aggr[dst] += node_rep[src]
    k_scatter<<<scatter_blocks, 256>>>(node_rep, src, dst, p_lift);

    // 2) y1 = concat(lift, edge) @ Wa  [E,128]
    k_gemm_mma<1, 256><<<dim3(gridE, 1), 256, SMEM>>>(
        p_lift, edge_rep, nullptr, nullptr, nullptr, p_wt + 0 * 65536,
        p_y1, EE, 128, p_sum + 0, p_sumsq + 0);
    k_finalize<<<1, 256>>>(128, 1.f / EE, ga, ba, p_sum + 0, p_sumsq + 0, p_scale + 0, p_shift + 0);
    k_apply<<<2048, 256>>>(p_y1, (long long)EE * HH / 4, 31, p_scale + 0, p_shift + 0);

    // 3) lvl_aggr[src] += y1[dst]
    k_scatter<<<scatter_blocks, 256>>>(p_y1, dst, src, p_lvl);

    // 4) node branch
    k_gemm_mma<2, 128><<<dim3(gridN, 2), 256, SMEM>>>(
        node_rep, p_lvl, nullptr, nullptr, eps1, p_wt + 1 * 65536,
        p_yb1, NN, 256, p_sum + 256, p_sumsq + 256);
    k_finalize<<<1, 256>>>(256, 1.f / NN, gb1, bb1, p_sum + 256, p_sumsq + 256, p_scale + 256, p_shift + 256);
    k_gemm_mma<3, 256><<<dim3(gridN, 1), 256, SMEM>>>(
        p_yb1, nullptr, p_scale + 256, p_shift + 256, nullptr, p_wt + 2 * 65536,
        out_node, NN, 128, p_sum + 512, p_sumsq + 512);
    k_finalize<<<1, 256>>>(128, 1.f / NN, gb2, bb2, p_sum + 512, p_sumsq + 512, p_scale + 512, p_shift + 512);
    k_apply<<<2048, 256>>>(out_node, (long long)NN * HH / 4, 31, p_scale + 512, p_shift + 512);

    // 5) edge branch
    k_gemm_mma<2, 128><<<dim3(gridE, 2), 256, SMEM>>>(
        edge_rep, p_lift, nullptr, nullptr, eps2, p_wt + 3 * 65536,
        p_yl1, EE, 256, p_sum + 768, p_sumsq + 768);
    k_finalize<<<1, 256>>>(256, 1.f / EE, gl1, bl1, p_sum + 768, p_sumsq + 768, p_scale + 768, p_shift + 768);
    k_gemm_mma<3, 256><<<dim3(gridE, 1), 256, SMEM>>>(
        p_yl1, nullptr, p_scale + 768, p_shift + 768, nullptr, p_wt + 4 * 65536,
        out_edge, EE, 128, p_sum + 1024, p_sumsq + 1024);
    k_finalize<<<1, 256>>>(128, 1.f / EE, gl2, bl2, p_sum + 1024, p_sumsq + 1024, p_scale + 1024, p_shift + 1024);
    k_apply<<<2048, 256>>>(out_edge, (long long)EE * HH / 4, 31, p_scale + 1024, p_shift + 1024);
}

// round 4
// speedup vs baseline: 1.7950x; 1.1677x over previous
#include <cuda_runtime.h>
#include <cstdint>

#define NN 50000
#define EE 400000
#define MM 800000
#define HH 128
#define HM 256
#define BN_EPS 1e-5f

// ---------------- device scratch ----------------
__device__ float g_lift[(size_t)EE * HH];
__device__ float g_y1  [(size_t)EE * HH];
__device__ float g_lvl [(size_t)NN * HH];
__device__ float g_yb1 [(size_t)NN * HM];
__device__ float g_yl1 [(size_t)EE * HM];
__device__ float g_wt  [5 * 65536];          // transposed weights [N,K]
__device__ float g_sum  [5 * 256];
__device__ float g_sumsq[5 * 256];
__device__ float g_scale[5 * 256];
__device__ float g_shift[5 * 256];

// ---------------- helpers ----------------
__device__ __forceinline__ float f2tf(float x) {
    uint32_t r;
    asm("cvt.rna.tf32.f32 %0, %1;" : "=r"(r) : "f"(x));
    return __uint_as_float(r);
}
__device__ __forceinline__ void mma_tf32(float* c, const uint32_t* a, const uint32_t* b) {
    asm volatile("mma.sync.aligned.m16n8k8.row.col.f32.tf32.tf32.f32 "
                 "{%0,%1,%2,%3}, {%4,%5,%6,%7}, {%8,%9}, {%0,%1,%2,%3};"
                 : "+f"(c[0]), "+f"(c[1]), "+f"(c[2]), "+f"(c[3])
                 : "r"(a[0]), "r"(a[1]), "r"(a[2]), "r"(a[3]),
                   "r"(b[0]), "r"(b[1]));
}
__device__ __forceinline__ void red_add_v4(float* p, float4 v) {
    asm volatile("red.global.add.v4.f32 [%0], {%1,%2,%3,%4};"
                 :: "l"(p), "f"(v.x), "f"(v.y), "f"(v.z), "f"(v.w) : "memory");
}

// ---------------- scatter: out[sidx[m]] += vals[gidx[m]] (rows of 128) ----------------
__global__ void k_scatter(const float* __restrict__ vals,
                          const int*   __restrict__ gidx,
                          const int*   __restrict__ sidx,
                          float*       __restrict__ out)
{
    int t = blockIdx.x * blockDim.x + threadIdx.x;
    int m = t >> 5;
    if (m >= MM) return;
    int lane = t & 31;
    int g = __ldg(gidx + m);
    int s = __ldg(sidx + m);
    float4 v = *(const float4*)(vals + (size_t)g * HH + lane * 4);
    red_add_v4(out + (size_t)s * HH + lane * 4, v);
}

// ---------------- scatter with fused BN-ReLU on the gathered rows ----------------
__global__ void k_scatter_bn(const float* __restrict__ vals,
                             const int*   __restrict__ gidx,
                             const int*   __restrict__ sidx,
                             const float* __restrict__ scale,
                             const float* __restrict__ shift,
                             float*       __restrict__ out)
{
    int t = blockIdx.x * blockDim.x + threadIdx.x;
    int m = t >> 5;
    if (m >= MM) return;
    int lane = t & 31;
    int g = __ldg(gidx + m);
    int s = __ldg(sidx + m);
    float4 v  = *(const float4*)(vals + (size_t)g * HH + lane * 4);
    float4 sc = *(const float4*)(scale + lane * 4);
    float4 sh = *(const float4*)(shift + lane * 4);
    v.x = fmaxf(fmaf(v.x, sc.x, sh.x), 0.f);
    v.y = fmaxf(fmaf(v.y, sc.y, sh.y), 0.f);
    v.z = fmaxf(fmaf(v.z, sc.z, sh.z), 0.f);
    v.w = fmaxf(fmaf(v.w, sc.w, sh.w), 0.f);
    red_add_v4(out + (size_t)s * HH + lane * 4, v);
}

// ---------------- weight transpose: Wt[n*K+k] = W[k*NC+n] ----------------
__global__ void k_transpose(const float* __restrict__ W, float* __restrict__ Wt, int K, int NC)
{
    int i = blockIdx.x * blockDim.x + threadIdx.x;
    if (i < K * NC) {
        int k = i / NC, n = i % NC;
        Wt[(size_t)n * K + k] = W[i];
    }
}

// ---------------- tf32 mma.sync GEMM: C[Rows,Ncols] = A[Rows,K] @ Bt^T ----------------
// CTA tile 128x128 (blockIdx.y = 128-col slice). Fused BN column stats in epilogue.
// MODE 1: A = concat(A0[.,128], A1[.,128])   (K=256)
// MODE 2: A = (1+*epsp)*A0 + A1              (K=128)
// MODE 3: A = relu(A0*scl[k] + shf[k])       (K=256, BN-ReLU fused on load)
template <int MODE, int K>
__global__ __launch_bounds__(256)
void k_gemm_mma(const float* __restrict__ A0, const float* __restrict__ A1,
                const float* __restrict__ scl, const float* __restrict__ shf,
                const float* __restrict__ epsp,
                const float* __restrict__ Bt,      // [Ncols, K]
                float* __restrict__ C, int Rows, int Ncols,
                float* __restrict__ osum, float* __restrict__ osumsq)
{
    extern __shared__ float smem[];
    float* sA = smem;          // [2][4096] fragment-order A tiles
    float* sB = smem + 8192;   // [2][4096] fragment-order B tiles

    constexpr int NCH = K / 32;

    int tid = threadIdx.x;
    int lane = tid & 31, wid = tid >> 5;
    int wm = wid >> 1, wn = wid & 1;          // 4x2 warp grid
    int r0 = blockIdx.x * 128;
    int c0 = blockIdx.y * 128;
    const float* Bs = Bt + (size_t)c0 * K;

    float et = 1.0f;
    if (MODE == 2) et = 1.0f + *epsp;

    float4 areg[4], breg[4];

    auto loadA = [&](int ch) {
        int kt = ch * 32;
#pragma unroll
        for (int i = 0; i < 4; i++) {
            int idx = i * 256 + tid;
            int row = idx >> 3, q = idx & 7;
            int gr = r0 + row, k = kt + q * 4;
            float4 v = make_float4(0.f, 0.f, 0.f, 0.f);
            if (gr < Rows) {
                if (MODE == 1) {
                    const float* s = (k < 128) ? A0 + (size_t)gr * 128 + k
                                               : A1 + (size_t)gr * 128 + (k - 128);
                    v = *(const float4*)s;
                } else if (MODE == 2) {
                    float4 x = *(const float4*)(A0 + (size_t)gr * 128 + k);
                    float4 y = *(const float4*)(A1 + (size_t)gr * 128 + k);
                    v.x = fmaf(et, x.x, y.x); v.y = fmaf(et, x.y, y.y);
                    v.z = fmaf(et, x.z, y.z); v.w = fmaf(et, x.w, y.w);
                } else {
                    float4 r4 = *(const float4*)(A0 + (size_t)gr * K + k);
                    float4 s4 = *(const float4*)(scl + k);
                    float4 h4 = *(const float4*)(shf + k);
                    v.x = fmaxf(fmaf(r4.x, s4.x, h4.x), 0.f);
                    v.y = fmaxf(fmaf(r4.y, s4.y, h4.y), 0.f);
                    v.z = fmaxf(fmaf(r4.z, s4.z, h4.z), 0.f);
                    v.w = fmaxf(fmaf(r4.w, s4.w, h4.w), 0.f);
                }
            }
            areg[i] = v;
        }
    };
    auto loadB = [&](int ch) {
        int kt = ch * 32;
#pragma unroll
        for (int i = 0; i < 4; i++) {
            int idx = i * 256 + tid;
            int n = idx >> 3, q = idx & 7;
            breg[i] = *(const float4*)(Bs + (size_t)n * K + kt + q * 4);
        }
    };
    auto stsA = [&](int buf) {
        float* d = sA + buf * 4096;
#pragma unroll
        for (int i = 0; i < 4; i++) {
            int idx = i * 256 + tid;
            int row = idx >> 3, q = idx & 7;
            int mt = row >> 4, ks = q >> 1;
            int r = ((row >> 3) & 1) + 2 * (q & 1);
            int base = ((mt * 4 + ks) * 32 + (row & 7) * 4) * 4 + r;
            d[base + 0 ] = f2tf(areg[i].x);
            d[base + 4 ] = f2tf(areg[i].y);
            d[base + 8 ] = f2tf(areg[i].z);
            d[base + 12] = f2tf(areg[i].w);
        }
    };
    auto stsB = [&](int buf) {
        float* d = sB + buf * 4096;
#pragma unroll
        for (int i = 0; i < 4; i++) {
            int idx = i * 256 + tid;
            int n = idx >> 3, q = idx & 7;
            int nt = n >> 3, ks = q >> 1, r = q & 1;
            int base = ((nt * 4 + ks) * 32 + (n & 7) * 4) * 2 + r;
            d[base + 0] = f2tf(breg[i].x);
            d[base + 2] = f2tf(breg[i].y);
            d[base + 4] = f2tf(breg[i].z);
            d[base + 6] = f2tf(breg[i].w);
        }
    };

    float acc[2][8][4];
#pragma unroll
    for (int mt = 0; mt < 2; mt++)
#pragma unroll
        for (int nt = 0; nt < 8; nt++)
#pragma unroll
            for (int r = 0; r < 4; r++) acc[mt][nt][r] = 0.f;

    loadA(0); loadB(0);
    stsA(0);  stsB(0);
    __syncthreads();

    for (int ch = 0; ch < NCH; ch++) {
        if (ch + 1 < NCH) { loadA(ch + 1); loadB(ch + 1); }
        int buf = ch & 1;
        const float* pa = sA + buf * 4096;
        const float* pb = sB + buf * 4096;
#pragma unroll
        for (int ks = 0; ks < 4; ks++) {
            uint4 av[2];
            uint2 bv[8];
#pragma unroll
            for (int mt = 0; mt < 2; mt++)
                av[mt] = *(const uint4*)(pa + (((wm * 2 + mt) * 4 + ks) * 32 + lane) * 4);
#pragma unroll
            for (int nt = 0; nt < 8; nt++)
                bv[nt] = *(const uint2*)(pb + (((wn * 8 + nt) * 4 + ks) * 32 + lane) * 2);
#pragma unroll
            for (int mt = 0; mt < 2; mt++)
#pragma unroll
                for (int nt = 0; nt < 8; nt++)
                    mma_tf32(acc[mt][nt], (const uint32_t*)&av[mt], (const uint32_t*)&bv[nt]);
        }
        if (ch + 1 < NCH) { stsA(buf ^ 1); stsB(buf ^ 1); }
        __syncthreads();
    }

    // ---- epilogue: store C + fused column stats ----
    int g = lane >> 2, t = lane & 3;
#pragma unroll
    for (int mt = 0; mt < 2; mt++) {
        int ra = r0 + wm * 32 + mt * 16 + g;
        int rb = ra + 8;
#pragma unroll
        for (int nt = 0; nt < 8; nt++) {
            int col = c0 + wn * 64 + nt * 8 + 2 * t;
            if (ra < Rows) {
                float2 v = make_float2(acc[mt][nt][0], acc[mt][nt][1]);
                *(float2*)(C + (size_t)ra * Ncols + col) = v;
            }
            if (rb < Rows) {
                float2 v = make_float2(acc[mt][nt][2], acc[mt][nt][3]);
                *(float2*)(C + (size_t)rb * Ncols + col) = v;
            }
        }
    }
#pragma unroll
    for (int nt = 0; nt < 8; nt++) {
#pragma unroll
        for (int p = 0; p < 2; p++) {
            float a0 = acc[0][nt][p],     a1 = acc[0][nt][p + 2];
            float a2 = acc[1][nt][p],     a3 = acc[1][nt][p + 2];
            float s  = a0 + a1 + a2 + a3;
            float ss = a0 * a0 + a1 * a1 + a2 * a2 + a3 * a3;
#pragma unroll
            for (int off = 4; off < 32; off <<= 1) {
                s  += __shfl_xor_sync(0xFFFFFFFFu, s,  off);
                ss += __shfl_xor_sync(0xFFFFFFFFu, ss, off);
            }
            if (g == 0) {
                int col = c0 + wn * 64 + nt * 8 + 2 * t + p;
                atomicAdd(osum + col, s);
                atomicAdd(osumsq + col, ss);
            }
        }
    }
}

// ---------------- BN scale/shift from sums ----------------
__global__ void k_finalize(int C, float invR,
                           const float* __restrict__ g, const float* __restrict__ b,
                           const float* __restrict__ sum, const float* __restrict__ sumsq,
                           float* __restrict__ scale, float* __restrict__ shift)
{
    int c = threadIdx.x;
    if (c < C) {
        float m   = sum[c] * invR;
        float var = sumsq[c] * invR - m * m;
        float s   = g[c] * rsqrtf(var + BN_EPS);
        scale[c] = s;
        shift[c] = b[c] - m * s;
    }
}

// ---------------- in-place BN affine + ReLU ----------------
__global__ void k_apply(float* __restrict__ X, long long n4, int cmask4,
                        const float* __restrict__ scale, const float* __restrict__ shift)
{
    for (long long idx = blockIdx.x * (long long)blockDim.x + threadIdx.x; idx < n4;
         idx += (long long)gridDim.x * blockDim.x) {
        int c4 = (int)(idx & cmask4);
        float4 v  = ((float4*)X)[idx];
        float4 sc = *(const float4*)(scale + c4 * 4);
        float4 sh = *(const float4*)(shift + c4 * 4);
        v.x = fmaxf(fmaf(v.x, sc.x, sh.x), 0.f);
        v.y = fmaxf(fmaf(v.y, sc.y, sh.y), 0.f);
        v.z = fmaxf(fmaf(v.z, sc.z, sh.z), 0.f);
        v.w = fmaxf(fmaf(v.w, sc.w, sh.w), 0.f);
        ((float4*)X)[idx] = v;
    }
}

// ---------------- launch ----------------
extern "C" void kernel_launch(void* const* d_in, const int* in_sizes, int n_in,
                              void* d_out, int out_size)
{
    const float* node_rep = (const float*)d_in[0];
    const float* edge_rep = (const float*)d_in[1];
    const int*   n2e      = (const int*)  d_in[2];
    const int*   src = n2e;
    const int*   dst = n2e + MM;
    const float* Wa  = (const float*)d_in[3];
    const float* ga  = (const float*)d_in[4];
    const float* ba  = (const float*)d_in[5];
    const float* Wb1 = (const float*)d_in[6];
    const float* gb1 = (const float*)d_in[7];
    const float* bb1 = (const float*)d_in[8];
    const float* Wb2 = (const float*)d_in[9];
    const float* gb2 = (const float*)d_in[10];
    const float* bb2 = (const float*)d_in[11];
    const float* Wl1 = (const float*)d_in[12];
    const float* gl1 = (const float*)d_in[13];
    const float* bl1 = (const float*)d_in[14];
    const float* Wl2 = (const float*)d_in[15];
    const float* gl2 = (const float*)d_in[16];
    const float* bl2 = (const float*)d_in[17];
    const float* eps1 = (const float*)d_in[18];
    const float* eps2 = (const float*)d_in[19];

    float* out_node = (float*)d_out;
    float* out_edge = out_node + (size_t)NN * HH;

    float *p_lift, *p_y1, *p_lvl, *p_yb1, *p_yl1, *p_wt;
    float *p_sum, *p_sumsq, *p_scale, *p_shift;
    cudaGetSymbolAddress((void**)&p_lift,  g_lift);
    cudaGetSymbolAddress((void**)&p_y1,    g_y1);
    cudaGetSymbolAddress((void**)&p_lvl,   g_lvl);
    cudaGetSymbolAddress((void**)&p_yb1,   g_yb1);
    cudaGetSymbolAddress((void**)&p_yl1,   g_yl1);
    cudaGetSymbolAddress((void**)&p_wt,    g_wt);
    cudaGetSymbolAddress((void**)&p_sum,   g_sum);
    cudaGetSymbolAddress((void**)&p_sumsq, g_sumsq);
    cudaGetSymbolAddress((void**)&p_scale, g_scale);
    cudaGetSymbolAddress((void**)&p_shift, g_shift);

    const int SMEM = 16384 * 4;   // 64 KB dynamic
    cudaFuncSetAttribute(k_gemm_mma<1, 256>, cudaFuncAttributeMaxDynamicSharedMemorySize, SMEM);
    cudaFuncSetAttribute(k_gemm_mma<2, 128>, cudaFuncAttributeMaxDynamicSharedMemorySize, SMEM);
    cudaFuncSetAttribute(k_gemm_mma<3, 256>, cudaFuncAttributeMaxDynamicSharedMemorySize, SMEM);

    cudaMemsetAsync(p_lift, 0, (size_t)EE * HH * sizeof(float));
    cudaMemsetAsync(p_lvl,  0, (size_t)NN * HH * sizeof(float));
    cudaMemsetAsync(p_sum,  0, 5 * 256 * sizeof(float));
    cudaMemsetAsync(p_sumsq,0, 5 * 256 * sizeof(float));

    // transpose weights -> [N, K]
    k_transpose<<<128, 256>>>(Wa,  p_wt + 0 * 65536, 256, 128);
    k_transpose<<<128, 256>>>(Wb1, p_wt + 1 * 65536, 128, 256);
    k_transpose<<<128, 256>>>(Wb2, p_wt + 2 * 65536, 256, 128);
    k_transpose<<<128, 256>>>(Wl1, p_wt + 3 * 65536, 128, 256);
    k_transpose<<<128, 256>>>(Wl2, p_wt + 4 * 65536, 256, 128);

    const int scatter_blocks = (MM * 32 + 255) / 256;
    const int gridE = (EE + 127) / 128;   // 3125
    const int gridN = (NN + 127) / 128;   // 391

    // 1) lift_aggr[dst] += node_rep[src]
    k_scatter<<<scatter_blocks, 256>>>(node_rep, src, dst, p_lift);

    // 2) y1 = concat(lift, edge) @ Wa  [E,128] (raw; BN fused into scatter below)
    k_gemm_mma<1, 256><<<dim3(gridE, 1), 256, SMEM>>>(
        p_lift, edge_rep, nullptr, nullptr, nullptr, p_wt + 0 * 65536,
        p_y1, EE, 128, p_sum + 0, p_sumsq + 0);
    k_finalize<<<1, 256>>>(128, 1.f / EE, ga, ba, p_sum + 0, p_sumsq + 0, p_scale + 0, p_shift + 0);

    // 3) lvl_aggr[src] += relu(bn(y1))[dst]   (BN-ReLU fused into gather)
    k_scatter_bn<<<scatter_blocks, 256>>>(p_y1, dst, src, p_scale + 0, p_shift + 0, p_lvl);

    // 4) node branch
    k_gemm_mma<2, 128><<<dim3(gridN, 2), 256, SMEM>>>(
        node_rep, p_lvl, nullptr, nullptr, eps1, p_wt + 1 * 65536,
        p_yb1, NN, 256, p_sum + 256, p_sumsq + 256);
    k_finalize<<<1, 256>>>(256, 1.f / NN, gb1, bb1, p_sum + 256, p_sumsq + 256, p_scale + 256, p_shift + 256);
    k_gemm_mma<3, 256><<<dim3(gridN, 1), 256, SMEM>>>(
        p_yb1, nullptr, p_scale + 256, p_shift + 256, nullptr, p_wt + 2 * 65536,
        out_node, NN, 128, p_sum + 512, p_sumsq + 512);
    k_finalize<<<1, 256>>>(128, 1.f / NN, gb2, bb2, p_sum + 512, p_sumsq + 512, p_scale + 512, p_shift + 512);
    k_apply<<<2048, 256>>>(out_node, (long long)NN * HH / 4, 31, p_scale + 512, p_shift + 512);

    // 5) edge branch
    k_gemm_mma<2, 128><<<dim3(gridE, 2), 256, SMEM>>>(
        edge_rep, p_lift, nullptr, nullptr, eps2, p_wt + 3 * 65536,
        p_yl1, EE, 256, p_sum + 768, p_sumsq + 768);
    k_finalize<<<1, 256>>>(256, 1.f / EE, gl1, bl1, p_sum + 768, p_sumsq + 768, p_scale + 768, p_shift + 768);
    k_gemm_mma<3, 256><<<dim3(gridE, 1), 256, SMEM>>>(
        p_yl1, nullptr, p_scale + 768, p_shift + 768, nullptr, p_wt + 4 * 65536,
        out_edge, EE, 128, p_sum + 1024, p_sumsq + 1024);
    k_finalize<<<1, 256>>>(128, 1.f / EE, gl2, bl2, p_sum + 1024, p_sumsq + 1024, p_scale + 1024, p_shift + 1024);
    k_apply<<<2048, 256>>>(out_edge, (long long)EE * HH / 4, 31, p_scale + 1024, p_shift + 1024);
}

// round 5
// speedup vs baseline: 2.1481x; 1.1967x over previous
#include <cuda_runtime.h>
#include <cstdint>

#define NN 50000
#define EE 400000
#define MM 800000
#define HH 128
#define HM 256
#define BN_EPS 1e-5f

// ---------------- device scratch ----------------
__device__ float g_lift[(size_t)EE * HH];
__device__ float g_y1  [(size_t)EE * HH];
__device__ float g_lvl [(size_t)NN * HH];
__device__ float g_yb1 [(size_t)NN * HM];
__device__ float g_yl1 [(size_t)EE * HM];
__device__ float g_wt  [5 * 32768];          // tf32 weights in B-fragment order
__device__ float g_sum  [5 * 256];
__device__ float g_sumsq[5 * 256];
__device__ float g_scale[5 * 256];
__device__ float g_shift[5 * 256];

// ---------------- helpers ----------------
__device__ __forceinline__ float f2tf(float x) {
    uint32_t r;
    asm("cvt.rna.tf32.f32 %0, %1;" : "=r"(r) : "f"(x));
    return __uint_as_float(r);
}
__device__ __forceinline__ uint32_t smem_u32(const void* p) {
    uint32_t a;
    asm("{ .reg .u64 t; cvta.to.shared.u64 t, %1; cvt.u32.u64 %0, t; }" : "=r"(a) : "l"(p));
    return a;
}
__device__ __forceinline__ void cp_async16(uint32_t d, const void* s) {
    asm volatile("cp.async.ca.shared.global [%0], [%1], 16;" :: "r"(d), "l"(s) : "memory");
}
__device__ __forceinline__ void cp_commit() {
    asm volatile("cp.async.commit_group;" ::: "memory");
}
__device__ __forceinline__ void cp_wait_all() {
    asm volatile("cp.async.wait_group 0;" ::: "memory");
}
__device__ __forceinline__ void mma_tf32(float* c, const uint32_t* a, const uint32_t* b) {
    asm volatile("mma.sync.aligned.m16n8k8.row.col.f32.tf32.tf32.f32 "
                 "{%0,%1,%2,%3}, {%4,%5,%6,%7}, {%8,%9}, {%0,%1,%2,%3};"
                 : "+f"(c[0]), "+f"(c[1]), "+f"(c[2]), "+f"(c[3])
                 : "r"(a[0]), "r"(a[1]), "r"(a[2]), "r"(a[3]),
                   "r"(b[0]), "r"(b[1]));
}
__device__ __forceinline__ void red_add_v4(float* p, float4 v) {
    asm volatile("red.global.add.v4.f32 [%0], {%1,%2,%3,%4};"
                 :: "l"(p), "f"(v.x), "f"(v.y), "f"(v.z), "f"(v.w) : "memory");
}

// ---------------- prep: zero scratch + build fragment-order tf32 weights ----------------
// wfrag layout per weight w (K x NC): for (n,k): ch=k>>5, klc=k&31,
//   idx = w*32768 + ch*NC*32 + (n>>3)*256 + (klc>>3)*64 + (n&7)*8 + (klc&3)*2 + ((klc>>2)&1)
__global__ void k_prep(const float* __restrict__ Wa,  const float* __restrict__ Wb1,
                       const float* __restrict__ Wb2, const float* __restrict__ Wl1,
                       const float* __restrict__ Wl2,
                       float* __restrict__ wfrag,
                       float* __restrict__ lift, float* __restrict__ lvl,
                       float* __restrict__ sums)
{
    long long t = (long long)blockIdx.x * blockDim.x + threadIdx.x;
    const long long stride = (long long)gridDim.x * blockDim.x;
    const long long n1 = (long long)EE * HH / 4;
    for (long long i = t; i < n1; i += stride)
        ((float4*)lift)[i] = make_float4(0.f, 0.f, 0.f, 0.f);
    const long long n2 = (long long)NN * HH / 4;
    for (long long i = t; i < n2; i += stride)
        ((float4*)lvl)[i] = make_float4(0.f, 0.f, 0.f, 0.f);
    if (t < 2560) sums[t] = 0.f;
    for (long long i = t; i < 5 * 32768; i += stride) {
        int w = (int)(i >> 15);
        int e = (int)(i & 32767);
        int K  = (w == 1 || w == 3) ? 128 : 256;
        int NC = 32768 / K;
        int k = e / NC, n = e % NC;
        const float* W = (w == 0) ? Wa : (w == 1) ? Wb1 : (w == 2) ? Wb2 : (w == 3) ? Wl1 : Wl2;
        int ch = k >> 5, klc = k & 31;
        int dst = w * 32768 + ch * NC * 32 + (n >> 3) * 256 + (klc >> 3) * 64 +
                  (n & 7) * 8 + (klc & 3) * 2 + ((klc >> 2) & 1);
        wfrag[dst] = f2tf(W[(size_t)k * NC + n]);
    }
}

// ---------------- scatter: out[sidx[m]] += vals[gidx[m]] (rows of 128) ----------------
__global__ void k_scatter(const float* __restrict__ vals,
                          const int*   __restrict__ gidx,
                          const int*   __restrict__ sidx,
                          float*       __restrict__ out)
{
    int t = blockIdx.x * blockDim.x + threadIdx.x;
    int m = t >> 5;
    if (m >= MM) return;
    int lane = t & 31;
    int g = __ldg(gidx + m);
    int s = __ldg(sidx + m);
    float4 v = *(const float4*)(vals + (size_t)g * HH + lane * 4);
    red_add_v4(out + (size_t)s * HH + lane * 4, v);
}

// ---------------- scatter with fused BN-ReLU on the gathered rows ----------------
__global__ void k_scatter_bn(const float* __restrict__ vals,
                             const int*   __restrict__ gidx,
                             const int*   __restrict__ sidx,
                             const float* __restrict__ scale,
                             const float* __restrict__ shift,
                             float*       __restrict__ out)
{
    int t = blockIdx.x * blockDim.x + threadIdx.x;
    int m = t >> 5;
    if (m >= MM) return;
    int lane = t & 31;
    int g = __ldg(gidx + m);
    int s = __ldg(sidx + m);
    float4 v  = *(const float4*)(vals + (size_t)g * HH + lane * 4);
    float4 sc = *(const float4*)(scale + lane * 4);
    float4 sh = *(const float4*)(shift + lane * 4);
    v.x = fmaxf(fmaf(v.x, sc.x, sh.x), 0.f);
    v.y = fmaxf(fmaf(v.y, sc.y, sh.y), 0.f);
    v.z = fmaxf(fmaf(v.z, sc.z, sh.z), 0.f);
    v.w = fmaxf(fmaf(v.w, sc.w, sh.w), 0.f);
    red_add_v4(out + (size_t)s * HH + lane * 4, v);
}

// ---------------- tf32 mma.sync GEMM: C[Rows,Ncols] = A[Rows,K] @ W^T ----------------
// B comes pre-fragmented+tf32 from g_wt via cp.async.
// MODE 1: A = concat(A0[.,128], A1[.,128])   (K=256)
// MODE 2: A = (1+*epsp)*A0 + A1              (K=128)
// MODE 3: A = relu(A0*scl[k] + shf[k])       (K=256, BN-ReLU fused on load)
template <int MODE, int K>
__global__ __launch_bounds__(256)
void k_gemm_mma(const float* __restrict__ A0, const float* __restrict__ A1,
                const float* __restrict__ scl, const float* __restrict__ shf,
                const float* __restrict__ epsp,
                const float* __restrict__ Bt,      // fragment-order tf32 weight
                float* __restrict__ C, int Rows, int Ncols,
                float* __restrict__ osum, float* __restrict__ osumsq)
{
    extern __shared__ float smem[];
    float* sA = smem;          // [2][4096] fragment-order A tiles
    float* sB = smem + 8192;   // [2][4096] fragment-order B tiles
    uint32_t sB_u32 = smem_u32(sB);

    constexpr int NCH = K / 32;

    int tid = threadIdx.x;
    int lane = tid & 31, wid = tid >> 5;
    int wm = wid >> 1, wn = wid & 1;          // 4x2 warp grid
    int r0 = blockIdx.x * 128;
    int c0 = blockIdx.y * 128;

    float et = 1.0f;
    if (MODE == 2) et = 1.0f + *epsp;

    float4 areg[4];

    auto loadA = [&](int ch) {
        int kt = ch * 32;
#pragma unroll
        for (int i = 0; i < 4; i++) {
            int idx = i * 256 + tid;
            int row = idx >> 3, q = idx & 7;
            int gr = r0 + row, k = kt + q * 4;
            float4 v = make_float4(0.f, 0.f, 0.f, 0.f);
            if (gr < Rows) {
                if (MODE == 1) {
                    const float* s = (k < 128) ? A0 + (size_t)gr * 128 + k
                                               : A1 + (size_t)gr * 128 + (k - 128);
                    v = *(const float4*)s;
                } else if (MODE == 2) {
                    float4 x = *(const float4*)(A0 + (size_t)gr * 128 + k);
                    float4 y = *(const float4*)(A1 + (size_t)gr * 128 + k);
                    v.x = fmaf(et, x.x, y.x); v.y = fmaf(et, x.y, y.y);
                    v.z = fmaf(et, x.z, y.z); v.w = fmaf(et, x.w, y.w);
                } else {
                    float4 r4 = *(const float4*)(A0 + (size_t)gr * K + k);
                    float4 s4 = *(const float4*)(scl + k);
                    float4 h4 = *(const float4*)(shf + k);
                    v.x = fmaxf(fmaf(r4.x, s4.x, h4.x), 0.f);
                    v.y = fmaxf(fmaf(r4.y, s4.y, h4.y), 0.f);
                    v.z = fmaxf(fmaf(r4.z, s4.z, h4.z), 0.f);
                    v.w = fmaxf(fmaf(r4.w, s4.w, h4.w), 0.f);
                }
            }
            areg[i] = v;
        }
    };
    auto stsA = [&](int buf) {
        float* d = sA + buf * 4096;
#pragma unroll
        for (int i = 0; i < 4; i++) {
            int idx = i * 256 + tid;
            int row = idx >> 3, q = idx & 7;
            int mt = row >> 4, ks = q >> 1;
            int r = ((row >> 3) & 1) + 2 * (q & 1);
            int base = ((mt * 4 + ks) * 32 + (row & 7) * 4) * 4 + r;
            d[base + 0 ] = f2tf(areg[i].x);
            d[base + 4 ] = f2tf(areg[i].y);
            d[base + 8 ] = f2tf(areg[i].z);
            d[base + 12] = f2tf(areg[i].w);
        }
    };
    auto cpB = [&](int ch, int buf) {
        const float* src = Bt + (size_t)ch * (Ncols * 32) + c0 * 32;
        uint32_t dst = sB_u32 + buf * 16384;
#pragma unroll
        for (int i = 0; i < 4; i++) {
            int idx = i * 256 + tid;
            cp_async16(dst + idx * 16, src + idx * 4);
        }
        cp_commit();
    };

    float acc[2][8][4];
#pragma unroll
    for (int mt = 0; mt < 2; mt++)
#pragma unroll
        for (int nt = 0; nt < 8; nt++)
#pragma unroll
            for (int r = 0; r < 4; r++) acc[mt][nt][r] = 0.f;

    cpB(0, 0);
    loadA(0);
    stsA(0);
    cp_wait_all();
    __syncthreads();

    for (int ch = 0; ch < NCH; ch++) {
        int buf = ch & 1;
        if (ch + 1 < NCH) { cpB(ch + 1, buf ^ 1); loadA(ch + 1); }
        const float* pa = sA + buf * 4096;
        const float* pb = sB + buf * 4096;
#pragma unroll
        for (int ks = 0; ks < 4; ks++) {
            uint4 av[2];
            uint2 bv[8];
#pragma unroll
            for (int mt = 0; mt < 2; mt++)
                av[mt] = *(const uint4*)(pa + (((wm * 2 + mt) * 4 + ks) * 32 + lane) * 4);
#pragma unroll
            for (int nt = 0; nt < 8; nt++)
                bv[nt] = *(const uint2*)(pb + (((wn * 8 + nt) * 4 + ks) * 32 + lane) * 2);
#pragma unroll
            for (int mt = 0; mt < 2; mt++)
#pragma unroll
                for (int nt = 0; nt < 8; nt++)
                    mma_tf32(acc[mt][nt], (const uint32_t*)&av[mt], (const uint32_t*)&bv[nt]);
        }
        if (ch + 1 < NCH) stsA(buf ^ 1);
        cp_wait_all();
        __syncthreads();
    }

    // ---- epilogue: store C + fused column stats ----
    int g = lane >> 2, t = lane & 3;
#pragma unroll
    for (int mt = 0; mt < 2; mt++) {
        int ra = r0 + wm * 32 + mt * 16 + g;
        int rb = ra + 8;
#pragma unroll
        for (int nt = 0; nt < 8; nt++) {
            int col = c0 + wn * 64 + nt * 8 + 2 * t;
            if (ra < Rows) {
                float2 v = make_float2(acc[mt][nt][0], acc[mt][nt][1]);
                *(float2*)(C + (size_t)ra * Ncols + col) = v;
            }
            if (rb < Rows) {
                float2 v = make_float2(acc[mt][nt][2], acc[mt][nt][3]);
                *(float2*)(C + (size_t)rb * Ncols + col) = v;
            }
        }
    }
#pragma unroll
    for (int nt = 0; nt < 8; nt++) {
#pragma unroll
        for (int p = 0; p < 2; p++) {
            float a0 = acc[0][nt][p],     a1 = acc[0][nt][p + 2];
            float a2 = acc[1][nt][p],     a3 = acc[1][nt][p + 2];
            float s  = a0 + a1 + a2 + a3;
            float ss = a0 * a0 + a1 * a1 + a2 * a2 + a3 * a3;
#pragma unroll
            for (int off = 4; off < 32; off <<= 1) {
                s  += __shfl_xor_sync(0xFFFFFFFFu, s,  off);
                ss += __shfl_xor_sync(0xFFFFFFFFu, ss, off);
            }
            if (g == 0) {
                int col = c0 + wn * 64 + nt * 8 + 2 * t + p;
                atomicAdd(osum + col, s);
                atomicAdd(osumsq + col, ss);
            }
        }
    }
}

// ---------------- BN scale/shift from sums ----------------
__global__ void k_finalize(int C, float invR,
                           const float* __restrict__ g, const float* __restrict__ b,
                           const float* __restrict__ sum, const float* __restrict__ sumsq,
                           float* __restrict__ scale, float* __restrict__ shift)
{
    int c = threadIdx.x;
    if (c < C) {
        float m   = sum[c] * invR;
        float var = sumsq[c] * invR - m * m;
        float s   = g[c] * rsqrtf(var + BN_EPS);
        scale[c] = s;
        shift[c] = b[c] - m * s;
    }
}

// ---------------- in-place BN affine + ReLU ----------------
__global__ void k_apply(float* __restrict__ X, long long n4, int cmask4,
                        const float* __restrict__ scale, const float* __restrict__ shift)
{
    for (long long idx = blockIdx.x * (long long)blockDim.x + threadIdx.x; idx < n4;
         idx += (long long)gridDim.x * blockDim.x) {
        int c4 = (int)(idx & cmask4);
        float4 v  = ((float4*)X)[idx];
        float4 sc = *(const float4*)(scale + c4 * 4);
        float4 sh = *(const float4*)(shift + c4 * 4);
        v.x = fmaxf(fmaf(v.x, sc.x, sh.x), 0.f);
        v.y = fmaxf(fmaf(v.y, sc.y, sh.y), 0.f);
        v.z = fmaxf(fmaf(v.z, sc.z, sh.z), 0.f);
        v.w = fmaxf(fmaf(v.w, sc.w, sh.w), 0.f);
        ((float4*)X)[idx] = v;
    }
}

// ---------------- launch ----------------
extern "C" void kernel_launch(void* const* d_in, const int* in_sizes, int n_in,
                              void* d_out, int out_size)
{
    const float* node_rep = (const float*)d_in[0];
    const float* edge_rep = (const float*)d_in[1];
    const int*   n2e      = (const int*)  d_in[2];
    const int*   src = n2e;
    const int*   dst = n2e + MM;
    const float* Wa  = (const float*)d_in[3];
    const float* ga  = (const float*)d_in[4];
    const float* ba  = (const float*)d_in[5];
    const float* Wb1 = (const float*)d_in[6];
    const float* gb1 = (const float*)d_in[7];
    const float* bb1 = (const float*)d_in[8];
    const float* Wb2 = (const float*)d_in[9];
    const float* gb2 = (const float*)d_in[10];
    const float* bb2 = (const float*)d_in[11];
    const float* Wl1 = (const float*)d_in[12];
    const float* gl1 = (const float*)d_in[13];
    const float* bl1 = (const float*)d_in[14];
    const float* Wl2 = (const float*)d_in[15];
    const float* gl2 = (const float*)d_in[16];
    const float* bl2 = (const float*)d_in[17];
    const float* eps1 = (const float*)d_in[18];
    const float* eps2 = (const float*)d_in[19];

    float* out_node = (float*)d_out;
    float* out_edge = out_node + (size_t)NN * HH;

    float *p_lift, *p_y1, *p_lvl, *p_yb1, *p_yl1, *p_wt;
    float *p_sum, *p_sumsq, *p_scale, *p_shift;
    cudaGetSymbolAddress((void**)&p_lift,  g_lift);
    cudaGetSymbolAddress((void**)&p_y1,    g_y1);
    cudaGetSymbolAddress((void**)&p_lvl,   g_lvl);
    cudaGetSymbolAddress((void**)&p_yb1,   g_yb1);
    cudaGetSymbolAddress((void**)&p_yl1,   g_yl1);
    cudaGetSymbolAddress((void**)&p_wt,    g_wt);
    cudaGetSymbolAddress((void**)&p_sum,   g_sum);
    cudaGetSymbolAddress((void**)&p_sumsq, g_sumsq);
    cudaGetSymbolAddress((void**)&p_scale, g_scale);
    cudaGetSymbolAddress((void**)&p_shift, g_shift);

    const int SMEM = 16384 * 4;   // 64 KB dynamic
    cudaFuncSetAttribute(k_gemm_mma<1, 256>, cudaFuncAttributeMaxDynamicSharedMemorySize, SMEM);
    cudaFuncSetAttribute(k_gemm_mma<2, 128>, cudaFuncAttributeMaxDynamicSharedMemorySize, SMEM);
    cudaFuncSetAttribute(k_gemm_mma<3, 256>, cudaFuncAttributeMaxDynamicSharedMemorySize, SMEM);

    // 0) prep: zero lift/lvl/stats + fragment tf32 weights (replaces memsets + transposes)
    k_prep<<<2048, 256>>>(Wa, Wb1, Wb2, Wl1, Wl2, p_wt, p_lift, p_lvl, p_sum);

    const int scatter_blocks = (MM * 32 + 255) / 256;
    const int gridE = (EE + 127) / 128;   // 3125
    const int gridN = (NN + 127) / 128;   // 391

    // 1) lift_aggr[dst] += node_rep[src]
    k_scatter<<<scatter_blocks, 256>>>(node_rep, src, dst, p_lift);

    // 2) y1 = concat(lift, edge) @ Wa  [E,128] (raw; BN fused into scatter below)
    k_gemm_mma<1, 256><<<dim3(gridE, 1), 256, SMEM>>>(
        p_lift, edge_rep, nullptr, nullptr, nullptr, p_wt + 0 * 32768,
        p_y1, EE, 128, p_sum + 0, p_sumsq + 0);
    k_finalize<<<1, 256>>>(128, 1.f / EE, ga, ba, p_sum + 0, p_sumsq + 0, p_scale + 0, p_shift + 0);

    // 3) lvl_aggr[src] += relu(bn(y1))[dst]   (BN-ReLU fused into gather)
    k_scatter_bn<<<scatter_blocks, 256>>>(p_y1, dst, src, p_scale + 0, p_shift + 0, p_lvl);

    // 4) node branch
    k_gemm_mma<2, 128><<<dim3(gridN, 2), 256, SMEM>>>(
        node_rep, p_lvl, nullptr, nullptr, eps1, p_wt + 1 * 32768,
        p_yb1, NN, 256, p_sum + 256, p_sumsq + 256);
    k_finalize<<<1, 256>>>(256, 1.f / NN, gb1, bb1, p_sum + 256, p_sumsq + 256, p_scale + 256, p_shift + 256);
    k_gemm_mma<3, 256><<<dim3(gridN, 1), 256, SMEM>>>(
        p_yb1, nullptr, p_scale + 256, p_shift + 256, nullptr, p_wt + 2 * 32768,
        out_node, NN, 128, p_sum + 512, p_sumsq + 512);
    k_finalize<<<1, 256>>>(128, 1.f / NN, gb2, bb2, p_sum + 512, p_sumsq + 512, p_scale + 512, p_shift + 512);
    k_apply<<<2048, 256>>>(out_node, (long long)NN * HH / 4, 31, p_scale + 512, p_shift + 512);

    // 5) edge branch
    k_gemm_mma<2, 128><<<dim3(gridE, 2), 256, SMEM>>>(
        edge_rep, p_lift, nullptr, nullptr, eps2, p_wt + 3 * 32768,
        p_yl1, EE, 256, p_sum + 768, p_sumsq + 768);
    k_finalize<<<1, 256>>>(256, 1.f / EE, gl1, bl1, p_sum + 768, p_sumsq + 768, p_scale + 768, p_shift + 768);
    k_gemm_mma<3, 256><<<dim3(gridE, 1), 256, SMEM>>>(
        p_yl1, nullptr, p_scale + 768, p_shift + 768, nullptr, p_wt + 4 * 32768,
        out_edge, EE, 128, p_sum + 1024, p_sumsq + 1024);
    k_finalize<<<1, 256>>>(128, 1.f / EE, gl2, bl2, p_sum + 1024, p_sumsq + 1024, p_scale + 1024, p_shift + 1024);
    k_apply<<<2048, 256>>>(out_edge, (long long)EE * HH / 4, 31, p_scale + 1024, p_shift + 1024);
}

// round 11
// speedup vs baseline: 2.1790x; 1.0144x over previous
#include <cuda_runtime.h>
#include <cstdint>

#define NN 50000
#define EE 400000
#define MM 800000
#define HH 128
#define HM 256
#define BN_EPS 1e-5f

// ---------------- device scratch ----------------
__device__ float g_lift[(size_t)EE * HH];
__device__ float g_y1  [(size_t)EE * HH];
__device__ float g_lvl [(size_t)NN * HH];
__device__ float g_yb1 [(size_t)NN * HM];
__device__ float g_yl1 [(size_t)EE * HM];
__device__ float g_wt  [5 * 32768];          // tf32 weights in B-fragment order
__device__ float g_sum  [5 * 256];
__device__ float g_sumsq[5 * 256];
__device__ float g_scale[5 * 256];
__device__ float g_shift[5 * 256];

// ---------------- helpers ----------------
__device__ __forceinline__ float f2tf(float x) {
    uint32_t r;
    asm("cvt.rna.tf32.f32 %0, %1;" : "=r"(r) : "f"(x));
    return __uint_as_float(r);
}
__device__ __forceinline__ uint32_t smem_u32(const void* p) {
    uint32_t a;
    asm("{ .reg .u64 t; cvta.to.shared.u64 t, %1; cvt.u32.u64 %0, t; }" : "=r"(a) : "l"(p));
    return a;
}
__device__ __forceinline__ void cp_async16(uint32_t d, const void* s) {
    asm volatile("cp.async.ca.shared.global [%0], [%1], 16;" :: "r"(d), "l"(s) : "memory");
}
__device__ __forceinline__ void cp_commit() {
    asm volatile("cp.async.commit_group;" ::: "memory");
}
__device__ __forceinline__ void cp_wait_all() {
    asm volatile("cp.async.wait_group 0;" ::: "memory");
}
__device__ __forceinline__ void mma_tf32(float* c, const uint32_t* a, const uint32_t* b) {
    asm volatile("mma.sync.aligned.m16n8k8.row.col.f32.tf32.tf32.f32 "
                 "{%0,%1,%2,%3}, {%4,%5,%6,%7}, {%8,%9}, {%0,%1,%2,%3};"
                 : "+f"(c[0]), "+f"(c[1]), "+f"(c[2]), "+f"(c[3])
                 : "r"(a[0]), "r"(a[1]), "r"(a[2]), "r"(a[3]),
                   "r"(b[0]), "r"(b[1]));
}
__device__ __forceinline__ void red_add_v4(float* p, float4 v) {
    asm volatile("red.global.add.v4.f32 [%0], {%1,%2,%3,%4};"
                 :: "l"(p), "f"(v.x), "f"(v.y), "f"(v.z), "f"(v.w) : "memory");
}

// ---------------- prep: zero scratch + build fragment-order tf32 weights ----------------
__global__ void k_prep(const float* __restrict__ Wa,  const float* __restrict__ Wb1,
                       const float* __restrict__ Wb2, const float* __restrict__ Wl1,
                       const float* __restrict__ Wl2,
                       float* __restrict__ wfrag,
                       float* __restrict__ lift, float* __restrict__ lvl,
                       float* __restrict__ sums)
{
    long long t = (long long)blockIdx.x * blockDim.x + threadIdx.x;
    const long long stride = (long long)gridDim.x * blockDim.x;
    const long long n1 = (long long)EE * HH / 4;
    for (long long i = t; i < n1; i += stride)
        ((float4*)lift)[i] = make_float4(0.f, 0.f, 0.f, 0.f);
    const long long n2 = (long long)NN * HH / 4;
    for (long long i = t; i < n2; i += stride)
        ((float4*)lvl)[i] = make_float4(0.f, 0.f, 0.f, 0.f);
    if (t < 2560) sums[t] = 0.f;
    for (long long i = t; i < 5 * 32768; i += stride) {
        int w = (int)(i >> 15);
        int e = (int)(i & 32767);
        int K  = (w == 1 || w == 3) ? 128 : 256;
        int NC = 32768 / K;
        int k = e / NC, n = e % NC;
        const float* W = (w == 0) ? Wa : (w == 1) ? Wb1 : (w == 2) ? Wb2 : (w == 3) ? Wl1 : Wl2;
        int ch = k >> 5, klc = k & 31;
        int dst = w * 32768 + ch * NC * 32 + (n >> 3) * 256 + (klc >> 3) * 64 +
                  (n & 7) * 8 + (klc & 3) * 2 + ((klc >> 2) & 1);
        wfrag[dst] = f2tf(W[(size_t)k * NC + n]);
    }
}

// ---------------- scatter: out[sidx[m]] += vals[gidx[m]] (rows of 128) ----------------
__global__ void k_scatter(const float* __restrict__ vals,
                          const int*   __restrict__ gidx,
                          const int*   __restrict__ sidx,
                          float*       __restrict__ out)
{
    int t = blockIdx.x * blockDim.x + threadIdx.x;
    int m = t >> 5;
    if (m >= MM) return;
    int lane = t & 31;
    int g = __ldg(gidx + m);
    int s = __ldg(sidx + m);
    float4 v = *(const float4*)(vals + (size_t)g * HH + lane * 4);
    red_add_v4(out + (size_t)s * HH + lane * 4, v);
}

// ---------------- scatter with fused BN-ReLU on the gathered rows ----------------
__global__ void k_scatter_bn(const float* __restrict__ vals,
                             const int*   __restrict__ gidx,
                             const int*   __restrict__ sidx,
                             const float* __restrict__ scale,
                             const float* __restrict__ shift,
                             float*       __restrict__ out)
{
    int t = blockIdx.x * blockDim.x + threadIdx.x;
    int m = t >> 5;
    if (m >= MM) return;
    int lane = t & 31;
    int g = __ldg(gidx + m);
    int s = __ldg(sidx + m);
    float4 v  = *(const float4*)(vals + (size_t)g * HH + lane * 4);
    float4 sc = *(const float4*)(scale + lane * 4);
    float4 sh = *(const float4*)(shift + lane * 4);
    v.x = fmaxf(fmaf(v.x, sc.x, sh.x), 0.f);
    v.y = fmaxf(fmaf(v.y, sc.y, sh.y), 0.f);
    v.z = fmaxf(fmaf(v.z, sc.z, sh.z), 0.f);
    v.w = fmaxf(fmaf(v.w, sc.w, sh.w), 0.f);
    red_add_v4(out + (size_t)s * HH + lane * 4, v);
}

// ---------------- tf32 mma.sync GEMM (B pre-fragmented via cp.async) ----------------
template <int MODE, int K>
__global__ __launch_bounds__(256, 2)
void k_gemm_mma(const float* __restrict__ A0, const float* __restrict__ A1,
                const float* __restrict__ scl, const float* __restrict__ shf,
                const float* __restrict__ epsp,
                const float* __restrict__ Bt,
                float* __restrict__ C, int Rows, int Ncols,
                float* __restrict__ osum, float* __restrict__ osumsq)
{
    extern __shared__ float smem[];
    float* sA = smem;          // [2][4096]
    float* sB = smem + 8192;   // [2][4096]
    uint32_t sB_u32 = smem_u32(sB);

    constexpr int NCH = K / 32;

    int tid = threadIdx.x;
    int lane = tid & 31, wid = tid >> 5;
    int wm = wid >> 1, wn = wid & 1;
    int r0 = blockIdx.x * 128;
    int c0 = blockIdx.y * 128;

    float et = 1.0f;
    if (MODE == 2) et = 1.0f + *epsp;

    float4 areg[4];

    auto loadA = [&](int ch) {
        int kt = ch * 32;
#pragma unroll
        for (int i = 0; i < 4; i++) {
            int idx = i * 256 + tid;
            int row = idx >> 3, q = idx & 7;
            int gr = r0 + row, k = kt + q * 4;
            float4 v = make_float4(0.f, 0.f, 0.f, 0.f);
            if (gr < Rows) {
                if (MODE == 1) {
                    const float* s = (k < 128) ? A0 + (size_t)gr * 128 + k
                                               : A1 + (size_t)gr * 128 + (k - 128);
                    v = *(const float4*)s;
                } else if (MODE == 2) {
                    float4 x = *(const float4*)(A0 + (size_t)gr * 128 + k);
                    float4 y = *(const float4*)(A1 + (size_t)gr * 128 + k);
                    v.x = fmaf(et, x.x, y.x); v.y = fmaf(et, x.y, y.y);
                    v.z = fmaf(et, x.z, y.z); v.w = fmaf(et, x.w, y.w);
                } else {
                    float4 r4 = *(const float4*)(A0 + (size_t)gr * K + k);
                    float4 s4 = *(const float4*)(scl + k);
                    float4 h4 = *(const float4*)(shf + k);
                    v.x = fmaxf(fmaf(r4.x, s4.x, h4.x), 0.f);
                    v.y = fmaxf(fmaf(r4.y, s4.y, h4.y), 0.f);
                    v.z = fmaxf(fmaf(r4.z, s4.z, h4.z), 0.f);
                    v.w = fmaxf(fmaf(r4.w, s4.w, h4.w), 0.f);
                }
            }
            areg[i] = v;
        }
    };
    auto stsA = [&](int buf) {
        float* d = sA + buf * 4096;
#pragma unroll
        for (int i = 0; i < 4; i++) {
            int idx = i * 256 + tid;
            int row = idx >> 3, q = idx & 7;
            int mt = row >> 4, ks = q >> 1;
            int r = ((row >> 3) & 1) + 2 * (q & 1);
            int base = ((mt * 4 + ks) * 32 + (row & 7) * 4) * 4 + r;
            d[base + 0 ] = f2tf(areg[i].x);
            d[base + 4 ] = f2tf(areg[i].y);
            d[base + 8 ] = f2tf(areg[i].z);
            d[base + 12] = f2tf(areg[i].w);
        }
    };
    auto cpB = [&](int ch, int buf) {
        const float* src = Bt + (size_t)ch * (Ncols * 32) + c0 * 32;
        uint32_t dst = sB_u32 + buf * 16384;
#pragma unroll
        for (int i = 0; i < 4; i++) {
            int idx = i * 256 + tid;
            cp_async16(dst + idx * 16, src + idx * 4);
        }
        cp_commit();
    };

    float acc[2][8][4];
#pragma unroll
    for (int mt = 0; mt < 2; mt++)
#pragma unroll
        for (int nt = 0; nt < 8; nt++)
#pragma unroll
            for (int r = 0; r < 4; r++) acc[mt][nt][r] = 0.f;

    cpB(0, 0);
    loadA(0);
    stsA(0);
    cp_wait_all();
    __syncthreads();

    for (int ch = 0; ch < NCH; ch++) {
        int buf = ch & 1;
        if (ch + 1 < NCH) { cpB(ch + 1, buf ^ 1); loadA(ch + 1); }
        const float* pa = sA + buf * 4096;
        const float* pb = sB + buf * 4096;
#pragma unroll
        for (int ks = 0; ks < 4; ks++) {
            uint4 av[2];
            uint2 bv[8];
#pragma unroll
            for (int mt = 0; mt < 2; mt++)
                av[mt] = *(const uint4*)(pa + (((wm * 2 + mt) * 4 + ks) * 32 + lane) * 4);
#pragma unroll
            for (int nt = 0; nt < 8; nt++)
                bv[nt] = *(const uint2*)(pb + (((wn * 8 + nt) * 4 + ks) * 32 + lane) * 2);
#pragma unroll
            for (int mt = 0; mt < 2; mt++)
#pragma unroll
                for (int nt = 0; nt < 8; nt++)
                    mma_tf32(acc[mt][nt], (const uint32_t*)&av[mt], (const uint32_t*)&bv[nt]);
        }
        if (ch + 1 < NCH) stsA(buf ^ 1);
        cp_wait_all();
        __syncthreads();
    }

    // ---- epilogue: store C + fused column stats ----
    int g = lane >> 2, t = lane & 3;
#pragma unroll
    for (int mt = 0; mt < 2; mt++) {
        int ra = r0 + wm * 32 + mt * 16 + g;
        int rb = ra + 8;
#pragma unroll
        for (int nt = 0; nt < 8; nt++) {
            int col = c0 + wn * 64 + nt * 8 + 2 * t;
            if (ra < Rows) {
                float2 v = make_float2(acc[mt][nt][0], acc[mt][nt][1]);
                *(float2*)(C + (size_t)ra * Ncols + col) = v;
            }
            if (rb < Rows) {
                float2 v = make_float2(acc[mt][nt][2], acc[mt][nt][3]);
                *(float2*)(C + (size_t)rb * Ncols + col) = v;
            }
        }
    }
#pragma unroll
    for (int nt = 0; nt < 8; nt++) {
#pragma unroll
        for (int p = 0; p < 2; p++) {
            float a0 = acc[0][nt][p],     a1 = acc[0][nt][p + 2];
            float a2 = acc[1][nt][p],     a3 = acc[1][nt][p + 2];
            float s  = a0 + a1 + a2 + a3;
            float ss = a0 * a0 + a1 * a1 + a2 * a2 + a3 * a3;
#pragma unroll
            for (int off = 4; off < 32; off <<= 1) {
                s  += __shfl_xor_sync(0xFFFFFFFFu, s,  off);
                ss += __shfl_xor_sync(0xFFFFFFFFu, ss, off);
            }
            if (g == 0) {
                int col = c0 + wn * 64 + nt * 8 + 2 * t + p;
                atomicAdd(osum + col, s);
                atomicAdd(osumsq + col, ss);
            }
        }
    }
}

// ---------------- BN scale/shift from sums ----------------
__global__ void k_finalize(int C, float invR,
                           const float* __restrict__ g, const float* __restrict__ b,
                           const float* __restrict__ sum, const float* __restrict__ sumsq,
                           float* __restrict__ scale, float* __restrict__ shift)
{
    int c = threadIdx.x;
    if (c < C) {
        float m   = sum[c] * invR;
        float var = sumsq[c] * invR - m * m;
        float s   = g[c] * rsqrtf(var + BN_EPS);
        scale[c] = s;
        shift[c] = b[c] - m * s;
    }
}

// ---------------- in-place BN affine + ReLU ----------------
__global__ void k_apply(float* __restrict__ X, long long n4, int cmask4,
                        const float* __restrict__ scale, const float* __restrict__ shift)
{
    for (long long idx = blockIdx.x * (long long)blockDim.x + threadIdx.x; idx < n4;
         idx += (long long)gridDim.x * blockDim.x) {
        int c4 = (int)(idx & cmask4);
        float4 v  = ((float4*)X)[idx];
        float4 sc = *(const float4*)(scale + c4 * 4);
        float4 sh = *(const float4*)(shift + c4 * 4);
        v.x = fmaxf(fmaf(v.x, sc.x, sh.x), 0.f);
        v.y = fmaxf(fmaf(v.y, sc.y, sh.y), 0.f);
        v.z = fmaxf(fmaf(v.z, sc.z, sh.z), 0.f);
        v.w = fmaxf(fmaf(v.w, sc.w, sh.w), 0.f);
        ((float4*)X)[idx] = v;
    }
}

// ---------------- launch ----------------
extern "C" void kernel_launch(void* const* d_in, const int* in_sizes, int n_in,
                              void* d_out, int out_size)
{
    const float* node_rep = (const float*)d_in[0];
    const float* edge_rep = (const float*)d_in[1];
    const int*   n2e      = (const int*)  d_in[2];
    const int*   src = n2e;
    const int*   dst = n2e + MM;
    const float* Wa  = (const float*)d_in[3];
    const float* ga  = (const float*)d_in[4];
    const float* ba  = (const float*)d_in[5];
    const float* Wb1 = (const float*)d_in[6];
    const float* gb1 = (const float*)d_in[7];
    const float* bb1 = (const float*)d_in[8];
    const float* Wb2 = (const float*)d_in[9];
    const float* gb2 = (const float*)d_in[10];
    const float* bb2 = (const float*)d_in[11];
    const float* Wl1 = (const float*)d_in[12];
    const float* gl1 = (const float*)d_in[13];
    const float* bl1 = (const float*)d_in[14];
    const float* Wl2 = (const float*)d_in[15];
    const float* gl2 = (const float*)d_in[16];
    const float* bl2 = (const float*)d_in[17];
    const float* eps1 = (const float*)d_in[18];
    const float* eps2 = (const float*)d_in[19];

    float* out_node = (float*)d_out;
    float* out_edge = out_node + (size_t)NN * HH;

    float *p_lift, *p_y1, *p_lvl, *p_yb1, *p_yl1, *p_wt;
    float *p_sum, *p_sumsq, *p_scale, *p_shift;
    cudaGetSymbolAddress((void**)&p_lift,  g_lift);
    cudaGetSymbolAddress((void**)&p_y1,    g_y1);
    cudaGetSymbolAddress((void**)&p_lvl,   g_lvl);
    cudaGetSymbolAddress((void**)&p_yb1,   g_yb1);
    cudaGetSymbolAddress((void**)&p_yl1,   g_yl1);
    cudaGetSymbolAddress((void**)&p_wt,    g_wt);
    cudaGetSymbolAddress((void**)&p_sum,   g_sum);
    cudaGetSymbolAddress((void**)&p_sumsq, g_sumsq);
    cudaGetSymbolAddress((void**)&p_scale, g_scale);
    cudaGetSymbolAddress((void**)&p_shift, g_shift);

    const int SMEM = 16384 * 4;   // 64 KB dynamic
    cudaFuncSetAttribute(k_gemm_mma<1, 256>, cudaFuncAttributeMaxDynamicSharedMemorySize, SMEM);
    cudaFuncSetAttribute(k_gemm_mma<2, 128>, cudaFuncAttributeMaxDynamicSharedMemorySize, SMEM);
    cudaFuncSetAttribute(k_gemm_mma<3, 256>, cudaFuncAttributeMaxDynamicSharedMemorySize, SMEM);

    // 0) prep
    k_prep<<<2048, 256>>>(Wa, Wb1, Wb2, Wl1, Wl2, p_wt, p_lift, p_lvl, p_sum);

    const int scatter_blocks = (MM * 32 + 255) / 256;
    const int gridE = (EE + 127) / 128;   // 3125
    const int gridN = (NN + 127) / 128;   // 391

    // 1) lift_aggr[dst] += node_rep[src]
    k_scatter<<<scatter_blocks, 256>>>(node_rep, src, dst, p_lift);

    // 2) y1 = concat(lift, edge) @ Wa  [E,128]
    k_gemm_mma<1, 256><<<dim3(gridE, 1), 256, SMEM>>>(
        p_lift, edge_rep, nullptr, nullptr, nullptr, p_wt + 0 * 32768,
        p_y1, EE, 128, p_sum + 0, p_sumsq + 0);
    k_finalize<<<1, 256>>>(128, 1.f / EE, ga, ba, p_sum + 0, p_sumsq + 0, p_scale + 0, p_shift + 0);

    // 3) lvl_aggr[src] += relu(bn(y1))[dst]
    k_scatter_bn<<<scatter_blocks, 256>>>(p_y1, dst, src, p_scale + 0, p_shift + 0, p_lvl);

    // 4) node branch
    k_gemm_mma<2, 128><<<dim3(gridN, 2), 256, SMEM>>>(
        node_rep, p_lvl, nullptr, nullptr, eps1, p_wt + 1 * 32768,
        p_yb1, NN, 256, p_sum + 256, p_sumsq + 256);
    k_finalize<<<1, 256>>>(256, 1.f / NN, gb1, bb1, p_sum + 256, p_sumsq + 256,
                           p_scale + 256, p_shift + 256);
    k_gemm_mma<3, 256><<<dim3(gridN, 1), 256, SMEM>>>(
        p_yb1, nullptr, p_scale + 256, p_shift + 256, nullptr, p_wt + 2 * 32768,
        out_node, NN, 128, p_sum + 512, p_sumsq + 512);
    k_finalize<<<1, 256>>>(128, 1.f / NN, gb2, bb2, p_sum + 512, p_sumsq + 512,
                           p_scale + 512, p_shift + 512);
    k_apply<<<2048, 256>>>(out_node, (long long)NN * HH / 4, 31, p_scale + 512, p_shift + 512);

    // 5) edge branch
    k_gemm_mma<2, 128><<<dim3(gridE, 2), 256, SMEM>>>(
        edge_rep, p_lift, nullptr, nullptr, eps2, p_wt + 3 * 32768,
        p_yl1, EE, 256, p_sum + 768, p_sumsq + 768);
    k_finalize<<<1, 256>>>(256, 1.f / EE, gl1, bl1, p_sum + 768, p_sumsq + 768,
                           p_scale + 768, p_shift + 768);
    k_gemm_mma<3, 256><<<dim3(gridE, 1), 256, SMEM>>>(
        p_yl1, nullptr, p_scale + 768, p_shift + 768, nullptr, p_wt + 4 * 32768,
        out_edge, EE, 128, p_sum + 1024, p_sumsq + 1024);
    k_finalize<<<1, 256>>>(128, 1.f / EE, gl2, bl2, p_sum + 1024, p_sumsq + 1024,
                           p_scale + 1024, p_shift + 1024);
    k_apply<<<2048, 256>>>(out_edge, (long long)EE * HH / 4, 31, p_scale + 1024, p_shift + 1024);
}